// round 11
// baseline (speedup 1.0000x reference)
#include <cuda_runtime.h>

// Problem constants
#define B_ 8
#define L_ 2048
#define H_ 256

// Scratch (device globals — no allocations allowed)
__device__ float d_Wh[B_ * L_ * H_];                     // 16.8 MB
__device__ float d_S[(long long)B_ * L_ * L_];           // 134 MB
__device__ float d_c[B_ * L_ * H_];                      // 16.8 MB
__device__ float d_m[B_ * L_];
__device__ float d_invZ[B_ * L_];

// ---------------------------------------------------------------------------
// Generic NT SGEMM: C[M,N] = A[M,K] * Bt[N,K]^T   (both A and Bt K-contiguous)
// 128x128 block tile, BK=8, 256 threads, 8x8 per thread. All dims % tile == 0.
// ---------------------------------------------------------------------------
__global__ __launch_bounds__(256) void sgemm_nt(
    const float* __restrict__ A, const float* __restrict__ Bt,
    float* __restrict__ C, int M, int N, int K,
    long long sA, long long sB, long long sC)
{
    A  += (long long)blockIdx.z * sA;
    Bt += (long long)blockIdx.z * sB;
    C  += (long long)blockIdx.z * sC;

    __shared__ __align__(16) float As[8][128];
    __shared__ __align__(16) float Bs[8][128];

    const int tid   = threadIdx.x;
    const int mBase = blockIdx.y * 128;
    const int nBase = blockIdx.x * 128;
    const int lr = tid >> 1;            // 0..127 (tile row for loads)
    const int lc = (tid & 1) << 2;      // 0 or 4 (k offset for loads)
    const int m0 = (tid >> 4) << 3;     // thread micro-tile row
    const int n0 = (tid & 15) << 3;     // thread micro-tile col

    float acc[8][8];
    #pragma unroll
    for (int i = 0; i < 8; ++i)
        #pragma unroll
        for (int j = 0; j < 8; ++j) acc[i][j] = 0.f;

    for (int k0 = 0; k0 < K; k0 += 8) {
        float4 av = *(const float4*)&A [(long long)(mBase + lr) * K + (k0 + lc)];
        float4 bv = *(const float4*)&Bt[(long long)(nBase + lr) * K + (k0 + lc)];
        As[lc + 0][lr] = av.x; As[lc + 1][lr] = av.y;
        As[lc + 2][lr] = av.z; As[lc + 3][lr] = av.w;
        Bs[lc + 0][lr] = bv.x; Bs[lc + 1][lr] = bv.y;
        Bs[lc + 2][lr] = bv.z; Bs[lc + 3][lr] = bv.w;
        __syncthreads();
        #pragma unroll
        for (int kk = 0; kk < 8; ++kk) {
            float4 a0 = *(const float4*)&As[kk][m0];
            float4 a1 = *(const float4*)&As[kk][m0 + 4];
            float4 b0 = *(const float4*)&Bs[kk][n0];
            float4 b1 = *(const float4*)&Bs[kk][n0 + 4];
            float a[8] = {a0.x, a0.y, a0.z, a0.w, a1.x, a1.y, a1.z, a1.w};
            float b[8] = {b0.x, b0.y, b0.z, b0.w, b1.x, b1.y, b1.z, b1.w};
            #pragma unroll
            for (int i = 0; i < 8; ++i)
                #pragma unroll
                for (int j = 0; j < 8; ++j)
                    acc[i][j] = fmaf(a[i], b[j], acc[i][j]);
        }
        __syncthreads();
    }

    #pragma unroll
    for (int i = 0; i < 8; ++i) {
        float* crow = &C[(long long)(mBase + m0 + i) * N + nBase + n0];
        *(float4*)&crow[0] = make_float4(acc[i][0], acc[i][1], acc[i][2], acc[i][3]);
        *(float4*)&crow[4] = make_float4(acc[i][4], acc[i][5], acc[i][6], acc[i][7]);
    }
}

// ---------------------------------------------------------------------------
// Column softmax stats over dim i: for each (b,j): m_j = max_i S[i,j],
// Z_j = sum_i exp(S[i,j]-m_j). Online single pass, coalesced (thread = col j).
// ---------------------------------------------------------------------------
__global__ void colstats_kernel()
{
    const int col = blockIdx.x * blockDim.x + threadIdx.x;   // 0..B*L-1
    const int b = col >> 11;            // / 2048
    const int j = col & (L_ - 1);
    const float* Sp = d_S + (long long)b * L_ * L_ + j;

    float m = -3.4e38f, Z = 0.f;
    #pragma unroll 4
    for (int i = 0; i < L_; ++i) {
        float x  = Sp[(long long)i * L_];
        float mn = fmaxf(m, x);
        Z = Z * __expf(m - mn) + __expf(x - mn);
        m = mn;
    }
    d_m[col]    = m;
    d_invZ[col] = 1.f / Z;
}

// ---------------------------------------------------------------------------
// c[b,i,h] = sum_j P[i,j] * g[b,j,h],  P[i,j] = exp(S[i,j]-m_j) * invZ_j
// NN GEMM (M=L, N=H, K=L) with the exp transform fused into the A-tile load.
// ---------------------------------------------------------------------------
__global__ __launch_bounds__(256) void attn_c_kernel(const float* __restrict__ g)
{
    const int b = blockIdx.z;
    const float* S     = d_S + (long long)b * L_ * L_;
    const float* gb    = g   + (long long)b * L_ * H_;
    float*       cb    = d_c + (long long)b * L_ * H_;
    const float* mcol  = d_m    + b * L_;
    const float* izcol = d_invZ + b * L_;

    __shared__ __align__(16) float As[8][128];
    __shared__ __align__(16) float Bs[8][128];

    const int tid   = threadIdx.x;
    const int mBase = blockIdx.y * 128;
    const int nBase = blockIdx.x * 128;
    const int lr = tid >> 1;
    const int lc = (tid & 1) << 2;
    const int kr = tid >> 5;            // 0..7  (B tile row)
    const int c4 = (tid & 31) << 2;     // 0..124 (B tile col)
    const int m0 = (tid >> 4) << 3;
    const int n0 = (tid & 15) << 3;

    float acc[8][8];
    #pragma unroll
    for (int i = 0; i < 8; ++i)
        #pragma unroll
        for (int j = 0; j < 8; ++j) acc[i][j] = 0.f;

    for (int k0 = 0; k0 < L_; k0 += 8) {
        const int j = k0 + lc;
        float4 av = *(const float4*)&S[(long long)(mBase + lr) * L_ + j];
        av.x = __expf(av.x - mcol[j + 0]) * izcol[j + 0];
        av.y = __expf(av.y - mcol[j + 1]) * izcol[j + 1];
        av.z = __expf(av.z - mcol[j + 2]) * izcol[j + 2];
        av.w = __expf(av.w - mcol[j + 3]) * izcol[j + 3];
        As[lc + 0][lr] = av.x; As[lc + 1][lr] = av.y;
        As[lc + 2][lr] = av.z; As[lc + 3][lr] = av.w;
        *(float4*)&Bs[kr][c4] =
            *(const float4*)&gb[(long long)(k0 + kr) * H_ + nBase + c4];
        __syncthreads();
        #pragma unroll
        for (int kk = 0; kk < 8; ++kk) {
            float4 a0 = *(const float4*)&As[kk][m0];
            float4 a1 = *(const float4*)&As[kk][m0 + 4];
            float4 b0 = *(const float4*)&Bs[kk][n0];
            float4 b1 = *(const float4*)&Bs[kk][n0 + 4];
            float a[8] = {a0.x, a0.y, a0.z, a0.w, a1.x, a1.y, a1.z, a1.w};
            float bb[8] = {b0.x, b0.y, b0.z, b0.w, b1.x, b1.y, b1.z, b1.w};
            #pragma unroll
            for (int i = 0; i < 8; ++i)
                #pragma unroll
                for (int jj = 0; jj < 8; ++jj)
                    acc[i][jj] = fmaf(a[i], bb[jj], acc[i][jj]);
        }
        __syncthreads();
    }

    #pragma unroll
    for (int i = 0; i < 8; ++i) {
        float* crow = &cb[(long long)(mBase + m0 + i) * H_ + nBase + n0];
        *(float4*)&crow[0] = make_float4(acc[i][0], acc[i][1], acc[i][2], acc[i][3]);
        *(float4*)&crow[4] = make_float4(acc[i][4], acc[i][5], acc[i][6], acc[i][7]);
    }
}

// ---------------------------------------------------------------------------
// out[m,o] = relu( sum_k cat[m,k] * W_out[o,k] + b_out[o] ),  K = 768.
// cat[m,k] synthesized on the fly: k<256 -> g, k<512 -> c, else g*c.
// (BK=8 tiles never straddle the 256-aligned segment boundaries.)
// ---------------------------------------------------------------------------
__global__ __launch_bounds__(256) void final_kernel(
    const float* __restrict__ g, const float* __restrict__ Wout,
    const float* __restrict__ bout, float* __restrict__ out)
{
    const int K = 3 * H_;   // 768
    const int N = H_;       // 256

    __shared__ __align__(16) float As[8][128];
    __shared__ __align__(16) float Bs[8][128];

    const int tid   = threadIdx.x;
    const int mBase = blockIdx.y * 128;
    const int nBase = blockIdx.x * 128;
    const int lr = tid >> 1;
    const int lc = (tid & 1) << 2;
    const int m0 = (tid >> 4) << 3;
    const int n0 = (tid & 15) << 3;

    float acc[8][8];
    #pragma unroll
    for (int i = 0; i < 8; ++i)
        #pragma unroll
        for (int j = 0; j < 8; ++j) acc[i][j] = 0.f;

    for (int k0 = 0; k0 < K; k0 += 8) {
        const int kg  = k0 + lc;
        const int seg = kg >> 8;
        const int kk  = kg & 255;
        const long long rowoff = (long long)(mBase + lr) * H_ + kk;
        float4 v;
        if (seg == 0) {
            v = *(const float4*)&g[rowoff];
        } else if (seg == 1) {
            v = *(const float4*)&d_c[rowoff];
        } else {
            float4 gv = *(const float4*)&g[rowoff];
            float4 cv = *(const float4*)&d_c[rowoff];
            v = make_float4(gv.x * cv.x, gv.y * cv.y, gv.z * cv.z, gv.w * cv.w);
        }
        As[lc + 0][lr] = v.x; As[lc + 1][lr] = v.y;
        As[lc + 2][lr] = v.z; As[lc + 3][lr] = v.w;
        float4 bv = *(const float4*)&Wout[(long long)(nBase + lr) * K + kg];
        Bs[lc + 0][lr] = bv.x; Bs[lc + 1][lr] = bv.y;
        Bs[lc + 2][lr] = bv.z; Bs[lc + 3][lr] = bv.w;
        __syncthreads();
        #pragma unroll
        for (int kq = 0; kq < 8; ++kq) {
            float4 a0 = *(const float4*)&As[kq][m0];
            float4 a1 = *(const float4*)&As[kq][m0 + 4];
            float4 b0 = *(const float4*)&Bs[kq][n0];
            float4 b1 = *(const float4*)&Bs[kq][n0 + 4];
            float a[8] = {a0.x, a0.y, a0.z, a0.w, a1.x, a1.y, a1.z, a1.w};
            float b[8] = {b0.x, b0.y, b0.z, b0.w, b1.x, b1.y, b1.z, b1.w};
            #pragma unroll
            for (int i = 0; i < 8; ++i)
                #pragma unroll
                for (int j = 0; j < 8; ++j)
                    acc[i][j] = fmaf(a[i], b[j], acc[i][j]);
        }
        __syncthreads();
    }

    float bj[8];
    #pragma unroll
    for (int j = 0; j < 8; ++j) bj[j] = bout[nBase + n0 + j];

    #pragma unroll
    for (int i = 0; i < 8; ++i) {
        float* orow = &out[(long long)(mBase + m0 + i) * N + nBase + n0];
        float r[8];
        #pragma unroll
        for (int j = 0; j < 8; ++j) r[j] = fmaxf(acc[i][j] + bj[j], 0.f);
        *(float4*)&orow[0] = make_float4(r[0], r[1], r[2], r[3]);
        *(float4*)&orow[4] = make_float4(r[4], r[5], r[6], r[7]);
    }
}

// ---------------------------------------------------------------------------
// Launch: 5 kernels on the default stream (graph-capturable, allocation-free)
// ---------------------------------------------------------------------------
extern "C" void kernel_launch(void* const* d_in, const int* in_sizes, int n_in,
                              void* d_out, int out_size)
{
    const float* g     = (const float*)d_in[0];
    const float* WP    = (const float*)d_in[1];
    const float* W_out = (const float*)d_in[2];
    const float* b_out = (const float*)d_in[3];
    float* out = (float*)d_out;

    void* pWh = nullptr;
    void* pS  = nullptr;
    cudaGetSymbolAddress(&pWh, d_Wh);
    cudaGetSymbolAddress(&pS, d_S);

    dim3 blk(256);

    // K1: Wh = g @ WP^T            M=16384, N=256, K=256
    sgemm_nt<<<dim3(H_ / 128, (B_ * L_) / 128, 1), blk>>>(
        g, WP, (float*)pWh, B_ * L_, H_, H_, 0, 0, 0);

    // K2: S_b = Wh_b @ g_b^T       per batch: M=N=2048, K=256
    sgemm_nt<<<dim3(L_ / 128, L_ / 128, B_), blk>>>(
        (float*)pWh, g, (float*)pS, L_, L_, H_,
        (long long)L_ * H_, (long long)L_ * H_, (long long)L_ * L_);

    // K3: per-column softmax stats (max + sumexp over dim i)
    colstats_kernel<<<(B_ * L_) / 256, 256>>>();

    // K4: c_b = softmax(S_b) @ g_b    per batch: M=2048, N=256, K=2048
    attn_c_kernel<<<dim3(H_ / 128, L_ / 128, B_), blk>>>(g);

    // K5: out = relu(concat(g,c,g*c) @ W_out^T + b_out)
    final_kernel<<<dim3(H_ / 128, (B_ * L_) / 128, 1), blk>>>(g, W_out, b_out, out);
}

// round 14
// speedup vs baseline: 2.6990x; 2.6990x over previous
#include <cuda_runtime.h>
#include <cuda_bf16.h>
#include <cstdint>

#define B_ 8
#define L_ 2048
#define H_ 256
#define BLH (B_ * L_ * H_)

// ---------------- device scratch (no allocations allowed) ----------------
__device__ float d_S[(long long)B_ * L_ * L_];            // 134 MB logits
__device__ float d_c[BLH];                                 // attention out fp32
__device__ float d_zp[8 * B_ * L_];                        // partial col sums
__device__ float d_invZ[B_ * L_];
__device__ __nv_bfloat16 d_g_hi[BLH],  d_g_lo[BLH];
__device__ __nv_bfloat16 d_gT_hi[BLH], d_gT_lo[BLH];       // per-batch g^T
__device__ __nv_bfloat16 d_Wh_hi[BLH], d_Wh_lo[BLH];
__device__ __nv_bfloat16 d_WP_hi[H_ * H_], d_WP_lo[H_ * H_];
__device__ __nv_bfloat16 d_Wo_hi[H_ * 3 * H_], d_Wo_lo[H_ * 3 * H_];

// ---------------- helpers ----------------
__device__ __forceinline__ uint32_t smem_u32(const void* p) {
    uint32_t a;
    asm("{ .reg .u64 t; cvta.to.shared.u64 t, %1; cvt.u32.u64 %0, t; }"
        : "=r"(a) : "l"(p));
    return a;
}

__device__ __forceinline__ void ldsm4(uint32_t* r, uint32_t addr) {
    asm volatile("ldmatrix.sync.aligned.m8n8.x4.shared.b16 {%0,%1,%2,%3}, [%4];"
                 : "=r"(r[0]), "=r"(r[1]), "=r"(r[2]), "=r"(r[3]) : "r"(addr));
}

__device__ __forceinline__ void mma16816(float* c, const uint32_t* a, const uint32_t* b) {
    asm volatile(
        "mma.sync.aligned.m16n8k16.row.col.f32.bf16.bf16.f32 "
        "{%0,%1,%2,%3}, {%4,%5,%6,%7}, {%8,%9}, {%0,%1,%2,%3};"
        : "+f"(c[0]), "+f"(c[1]), "+f"(c[2]), "+f"(c[3])
        : "r"(a[0]), "r"(a[1]), "r"(a[2]), "r"(a[3]), "r"(b[0]), "r"(b[1]));
}

// split 8 fp32 -> 8 bf16 hi + 8 bf16 lo (packed uint4 each)
__device__ __forceinline__ void split8(float4 a, float4 b, uint4& h, uint4& l) {
    __nv_bfloat162 h0 = __floats2bfloat162_rn(a.x, a.y);
    __nv_bfloat162 h1 = __floats2bfloat162_rn(a.z, a.w);
    __nv_bfloat162 h2 = __floats2bfloat162_rn(b.x, b.y);
    __nv_bfloat162 h3 = __floats2bfloat162_rn(b.z, b.w);
    float2 f0 = __bfloat1622float2(h0), f1 = __bfloat1622float2(h1);
    float2 f2 = __bfloat1622float2(h2), f3 = __bfloat1622float2(h3);
    __nv_bfloat162 l0 = __floats2bfloat162_rn(a.x - f0.x, a.y - f0.y);
    __nv_bfloat162 l1 = __floats2bfloat162_rn(a.z - f1.x, a.w - f1.y);
    __nv_bfloat162 l2 = __floats2bfloat162_rn(b.x - f2.x, b.y - f2.y);
    __nv_bfloat162 l3 = __floats2bfloat162_rn(b.z - f3.x, b.w - f3.y);
    h = make_uint4(*(uint32_t*)&h0, *(uint32_t*)&h1, *(uint32_t*)&h2, *(uint32_t*)&h3);
    l = make_uint4(*(uint32_t*)&l0, *(uint32_t*)&l1, *(uint32_t*)&l2, *(uint32_t*)&l3);
}

// ---------------------------------------------------------------------------
// Warp-MMA NT GEMM: C[M,N] = A[M,K] * B[N,K]^T with split-bf16 x 3 MMAs.
// Block 128x128, BK=32, 8 warps (2M x 4N), warp tile 64x32.
// MODE 0: Wh = g @ WP^T              (out split bf16)
// MODE 1: S  = Wh @ g^T  (per batch) (out fp32)
// MODE 2: c  = [exp(S-60)*invZ] @ gT^T (A built in loader, out fp32)
// MODE 3: out = relu(concat(g,c,g*c) @ Wo^T + b)
// ---------------------------------------------------------------------------
#define LDS 40   // smem row stride in bf16 elements (80 bytes, ldmatrix conflict-free)

template <int MODE>
__global__ __launch_bounds__(256) void mma_gemm(
    const float* __restrict__ g, const float* __restrict__ bout,
    float* __restrict__ out)
{
    constexpr int KDIM = (MODE == 2) ? 2048 : (MODE == 3 ? 768 : 256);
    constexpr int LDB  = (MODE == 2) ? 2048 : (MODE == 3 ? 768 : 256);

    __shared__ __align__(16) __nv_bfloat16 Ah_s[128 * LDS], Al_s[128 * LDS];
    __shared__ __align__(16) __nv_bfloat16 Bh_s[128 * LDS], Bl_s[128 * LDS];

    const int bz  = blockIdx.z;
    const int tid = threadIdx.x;
    const int wid = tid >> 5, lid = tid & 31;
    const int wm  = wid >> 2, wn = wid & 3;          // warp grid 2 x 4
    const int mBase = blockIdx.y * 128;
    const int nBase = blockIdx.x * 128;

    const __nv_bfloat16 *Agh = nullptr, *Agl = nullptr, *Bgh = nullptr, *Bgl = nullptr;
    const float *Sf = nullptr, *iz = nullptr;
    if (MODE == 0) { Agh = d_g_hi; Agl = d_g_lo; Bgh = d_WP_hi; Bgl = d_WP_lo; }
    if (MODE == 1) {
        const long long o = (long long)bz * L_ * H_;
        Agh = d_Wh_hi + o; Agl = d_Wh_lo + o; Bgh = d_g_hi + o; Bgl = d_g_lo + o;
    }
    if (MODE == 2) {
        Sf = d_S + (long long)bz * L_ * L_;
        iz = d_invZ + bz * L_;
        const long long o = (long long)bz * H_ * L_;
        Bgh = d_gT_hi + o; Bgl = d_gT_lo + o;
    }
    if (MODE == 3) { Bgh = d_Wo_hi; Bgl = d_Wo_lo; }

    float acc[4][4][4];
    #pragma unroll
    for (int i = 0; i < 4; ++i)
        #pragma unroll
        for (int j = 0; j < 4; ++j)
            #pragma unroll
            for (int q = 0; q < 4; ++q) acc[i][j][q] = 0.f;

    // loader mapping: thread -> (row, 16-elem k half)
    const int lrow = tid >> 1;
    const int lkb  = (tid & 1) << 4;

    // ldmatrix per-thread byte offsets
    const uint32_t sAh = smem_u32(Ah_s), sAl = smem_u32(Al_s);
    const uint32_t sBh = smem_u32(Bh_s), sBl = smem_u32(Bl_s);
    const uint32_t aoff = (uint32_t)((wm * 64 + (lid & 15)) * (LDS * 2) + (lid >> 4) * 16);
    const uint32_t boff = (uint32_t)((wn * 32 + ((lid >> 4) << 3) + (lid & 7)) * (LDS * 2)
                                     + ((lid >> 3) & 1) * 16);

    for (int k0 = 0; k0 < KDIM; k0 += 32) {
        // ---- B tile (always pre-split global bf16) ----
        #pragma unroll
        for (int it = 0; it < 2; ++it) {
            const int k = lkb + it * 8;
            const long long gi = (long long)(nBase + lrow) * LDB + k0 + k;
            *(uint4*)&Bh_s[lrow * LDS + k] = *(const uint4*)&Bgh[gi];
            *(uint4*)&Bl_s[lrow * LDS + k] = *(const uint4*)&Bgl[gi];
        }
        // ---- A tile ----
        if (MODE == 0 || MODE == 1) {
            #pragma unroll
            for (int it = 0; it < 2; ++it) {
                const int k = lkb + it * 8;
                const long long gi = (long long)(mBase + lrow) * 256 + k0 + k;
                *(uint4*)&Ah_s[lrow * LDS + k] = *(const uint4*)&Agh[gi];
                *(uint4*)&Al_s[lrow * LDS + k] = *(const uint4*)&Agl[gi];
            }
        } else if (MODE == 2) {
            #pragma unroll
            for (int it = 0; it < 2; ++it) {
                const int k  = lkb + it * 8;
                const int kg = k0 + k;
                const float* sp = Sf + (long long)(mBase + lrow) * 2048 + kg;
                float4 s0 = *(const float4*)sp;
                float4 s1 = *(const float4*)(sp + 4);
                float4 z0 = *(const float4*)(iz + kg);
                float4 z1 = *(const float4*)(iz + kg + 4);
                s0.x = __expf(s0.x - 60.f) * z0.x;
                s0.y = __expf(s0.y - 60.f) * z0.y;
                s0.z = __expf(s0.z - 60.f) * z0.z;
                s0.w = __expf(s0.w - 60.f) * z0.w;
                s1.x = __expf(s1.x - 60.f) * z1.x;
                s1.y = __expf(s1.y - 60.f) * z1.y;
                s1.z = __expf(s1.z - 60.f) * z1.z;
                s1.w = __expf(s1.w - 60.f) * z1.w;
                uint4 h, l;
                split8(s0, s1, h, l);
                *(uint4*)&Ah_s[lrow * LDS + k] = h;
                *(uint4*)&Al_s[lrow * LDS + k] = l;
            }
        } else { // MODE 3: concat(g, c, g*c)
            #pragma unroll
            for (int it = 0; it < 2; ++it) {
                const int k   = lkb + it * 8;
                const int kg  = k0 + k;
                const int seg = kg >> 8, kk = kg & 255;
                const long long ro = (long long)(mBase + lrow) * 256 + kk;
                float4 v0, v1;
                if (seg == 0) {
                    v0 = *(const float4*)&g[ro];
                    v1 = *(const float4*)&g[ro + 4];
                } else if (seg == 1) {
                    v0 = *(const float4*)&d_c[ro];
                    v1 = *(const float4*)&d_c[ro + 4];
                } else {
                    float4 g0 = *(const float4*)&g[ro];
                    float4 g1 = *(const float4*)&g[ro + 4];
                    float4 c0 = *(const float4*)&d_c[ro];
                    float4 c1 = *(const float4*)&d_c[ro + 4];
                    v0 = make_float4(g0.x * c0.x, g0.y * c0.y, g0.z * c0.z, g0.w * c0.w);
                    v1 = make_float4(g1.x * c1.x, g1.y * c1.y, g1.z * c1.z, g1.w * c1.w);
                }
                uint4 h, l;
                split8(v0, v1, h, l);
                *(uint4*)&Ah_s[lrow * LDS + k] = h;
                *(uint4*)&Al_s[lrow * LDS + k] = l;
            }
        }
        __syncthreads();

        #pragma unroll
        for (int ks = 0; ks < 2; ++ks) {
            uint32_t bh[4][2], bl[4][2];
            #pragma unroll
            for (int ntp = 0; ntp < 2; ++ntp) {
                uint32_t r[4];
                ldsm4(r, sBh + boff + (uint32_t)(ntp * 16 * LDS * 2 + ks * 32));
                bh[2 * ntp][0] = r[0]; bh[2 * ntp][1] = r[1];
                bh[2 * ntp + 1][0] = r[2]; bh[2 * ntp + 1][1] = r[3];
                ldsm4(r, sBl + boff + (uint32_t)(ntp * 16 * LDS * 2 + ks * 32));
                bl[2 * ntp][0] = r[0]; bl[2 * ntp][1] = r[1];
                bl[2 * ntp + 1][0] = r[2]; bl[2 * ntp + 1][1] = r[3];
            }
            #pragma unroll
            for (int mt = 0; mt < 4; ++mt) {
                uint32_t ah[4], al[4];
                ldsm4(ah, sAh + aoff + (uint32_t)(mt * 16 * LDS * 2 + ks * 32));
                ldsm4(al, sAl + aoff + (uint32_t)(mt * 16 * LDS * 2 + ks * 32));
                #pragma unroll
                for (int nt = 0; nt < 4; ++nt) {
                    mma16816(acc[mt][nt], ah, bh[nt]);
                    mma16816(acc[mt][nt], ah, bl[nt]);
                    mma16816(acc[mt][nt], al, bh[nt]);
                }
            }
        }
        __syncthreads();
    }

    // ---- epilogue ----
    const int er = lid >> 2;            // fragment row within 8
    const int ec = (lid & 3) << 1;      // fragment col pair
    #pragma unroll
    for (int mt = 0; mt < 4; ++mt) {
        #pragma unroll
        for (int nt = 0; nt < 4; ++nt) {
            const int row = mBase + wm * 64 + mt * 16 + er;
            const int col = nBase + wn * 32 + nt * 8 + ec;
            const float* a = acc[mt][nt];
            if (MODE == 1) {
                float* p = d_S + (long long)bz * L_ * L_;
                *(float2*)&p[(long long)row * 2048 + col]       = make_float2(a[0], a[1]);
                *(float2*)&p[(long long)(row + 8) * 2048 + col] = make_float2(a[2], a[3]);
            } else if (MODE == 2) {
                float* p = d_c + (long long)bz * L_ * H_;
                *(float2*)&p[(long long)row * 256 + col]       = make_float2(a[0], a[1]);
                *(float2*)&p[(long long)(row + 8) * 256 + col] = make_float2(a[2], a[3]);
            } else if (MODE == 0) {
                #pragma unroll
                for (int rr = 0; rr < 2; ++rr) {
                    const float x = a[rr * 2], y = a[rr * 2 + 1];
                    __nv_bfloat162 h = __floats2bfloat162_rn(x, y);
                    float2 f = __bfloat1622float2(h);
                    __nv_bfloat162 l = __floats2bfloat162_rn(x - f.x, y - f.y);
                    const long long o = (long long)(row + rr * 8) * 256 + col;
                    *(uint32_t*)&d_Wh_hi[o] = *(uint32_t*)&h;
                    *(uint32_t*)&d_Wh_lo[o] = *(uint32_t*)&l;
                }
            } else {
                const float b0 = bout[col], b1 = bout[col + 1];
                *(float2*)&out[(long long)row * 256 + col] =
                    make_float2(fmaxf(a[0] + b0, 0.f), fmaxf(a[1] + b1, 0.f));
                *(float2*)&out[(long long)(row + 8) * 256 + col] =
                    make_float2(fmaxf(a[2] + b0, 0.f), fmaxf(a[3] + b1, 0.f));
            }
        }
    }
}

// ---------------- small helper kernels ----------------
__global__ void split_kernel(const float* __restrict__ src,
                             __nv_bfloat16* __restrict__ hi,
                             __nv_bfloat16* __restrict__ lo, int n)
{
    const int i4 = (blockIdx.x * blockDim.x + threadIdx.x) * 4;
    if (i4 < n) {
        float4 v = *(const float4*)(src + i4);
        __nv_bfloat162 h0 = __floats2bfloat162_rn(v.x, v.y);
        __nv_bfloat162 h1 = __floats2bfloat162_rn(v.z, v.w);
        float2 f0 = __bfloat1622float2(h0), f1 = __bfloat1622float2(h1);
        __nv_bfloat162 l0 = __floats2bfloat162_rn(v.x - f0.x, v.y - f0.y);
        __nv_bfloat162 l1 = __floats2bfloat162_rn(v.z - f1.x, v.w - f1.y);
        *(uint2*)(hi + i4) = make_uint2(*(uint32_t*)&h0, *(uint32_t*)&h1);
        *(uint2*)(lo + i4) = make_uint2(*(uint32_t*)&l0, *(uint32_t*)&l1);
    }
}

// g -> g_hi/g_lo (row-major) and gT_hi/gT_lo (per-batch transpose)
__global__ void split_transpose_g(const float* __restrict__ g)
{
    __shared__ float tile[32][33];
    const int b  = blockIdx.z;
    const int h0 = blockIdx.x * 32, l0 = blockIdx.y * 32;
    const int tx = threadIdx.x, ty0 = threadIdx.y;
    const long long gb = (long long)b * L_ * H_;
    #pragma unroll
    for (int p = 0; p < 4; ++p) {
        const int ty = ty0 + p * 8;
        const float v = g[gb + (long long)(l0 + ty) * H_ + h0 + tx];
        tile[ty][tx] = v;
        __nv_bfloat16 h = __float2bfloat16(v);
        const long long o = gb + (long long)(l0 + ty) * H_ + h0 + tx;
        d_g_hi[o] = h;
        d_g_lo[o] = __float2bfloat16(v - __bfloat162float(h));
    }
    __syncthreads();
    #pragma unroll
    for (int p = 0; p < 4; ++p) {
        const int ty = ty0 + p * 8;
        const float v = tile[tx][ty];
        __nv_bfloat16 h = __float2bfloat16(v);
        const long long o = gb + (long long)(h0 + ty) * L_ + l0 + tx;
        d_gT_hi[o] = h;
        d_gT_lo[o] = __float2bfloat16(v - __bfloat162float(h));
    }
}

// Partial column sums of exp(S - 60): 8 row segments of 256 each.
__global__ void zpart_kernel()
{
    const int gid = blockIdx.x * 256 + threadIdx.x;   // 0 .. 8*16384-1
    const int seg = gid >> 14;
    const int col = gid & 16383;
    const int b = col >> 11, j = col & 2047;
    const float* Sp = d_S + (long long)b * L_ * L_ + (long long)(seg * 256) * L_ + j;
    float z = 0.f;
    #pragma unroll 4
    for (int i = 0; i < 256; ++i)
        z += __expf(Sp[(long long)i * L_] - 60.f);
    d_zp[(long long)seg * 16384 + col] = z;
}

__global__ void zfinal_kernel()
{
    const int col = blockIdx.x * 256 + threadIdx.x;
    float z = 0.f;
    #pragma unroll
    for (int s = 0; s < 8; ++s) z += d_zp[s * 16384 + col];
    d_invZ[col] = 1.f / z;
}

// ---------------- launch ----------------
extern "C" void kernel_launch(void* const* d_in, const int* in_sizes, int n_in,
                              void* d_out, int out_size)
{
    (void)in_sizes; (void)n_in; (void)out_size;
    const float* g     = (const float*)d_in[0];
    const float* WP    = (const float*)d_in[1];
    const float* W_out = (const float*)d_in[2];
    const float* b_out = (const float*)d_in[3];
    float* out = (float*)d_out;

    void *pWPh, *pWPl, *pWoh, *pWol;
    cudaGetSymbolAddress(&pWPh, d_WP_hi);
    cudaGetSymbolAddress(&pWPl, d_WP_lo);
    cudaGetSymbolAddress(&pWoh, d_Wo_hi);
    cudaGetSymbolAddress(&pWol, d_Wo_lo);

    // splits / transpose
    split_kernel<<<(H_ * H_ / 4 + 255) / 256, 256>>>(
        WP, (__nv_bfloat16*)pWPh, (__nv_bfloat16*)pWPl, H_ * H_);
    split_kernel<<<(H_ * 3 * H_ / 4 + 255) / 256, 256>>>(
        W_out, (__nv_bfloat16*)pWoh, (__nv_bfloat16*)pWol, H_ * 3 * H_);
    split_transpose_g<<<dim3(H_ / 32, L_ / 32, B_), dim3(32, 8)>>>(g);

    // K1: Wh = g @ WP^T             M=16384 N=256 K=256
    mma_gemm<0><<<dim3(2, 128, 1), 256>>>(g, nullptr, nullptr);
    // K2: S = Wh @ g^T (per batch)  M=N=2048 K=256
    mma_gemm<1><<<dim3(16, 16, B_), 256>>>(g, nullptr, nullptr);
    // Z (fixed-shift column sums over dim i)
    zpart_kernel<<<8 * B_ * L_ / 256, 256>>>();
    zfinal_kernel<<<B_ * L_ / 256, 256>>>();
    // K4: c = P @ g (per batch)     M=2048 N=256 K=2048
    mma_gemm<2><<<dim3(2, 16, B_), 256>>>(g, nullptr, nullptr);
    // K5: out = relu(concat @ Wo^T + b)  M=16384 N=256 K=768
    mma_gemm<3><<<dim3(2, 128, 1), 256>>>(g, b_out, out);
}